// round 1
// baseline (speedup 1.0000x reference)
#include <cuda_runtime.h>
#include <math.h>

#define Bb 16
#define Cc 256
#define Hh 64
#define Ww 64
#define EPSV 1e-5f

// ---------------- scratch (no allocations allowed) ----------------
__device__ float g_colsum[Bb*Cc*Ww];   // S[b,c,w] = sum_h x[b,c,h,w]
__device__ float g_qsum  [Bb*Cc*Ww];   // sum_h fq[b,c,h,w]
__device__ float g_ksum  [Bb*Ww];      // sum_{c,h} fk[b,c,h,w]
__device__ float g_wkred [Cc*9];       // sum_c wk[c, c', kh, kw]
__device__ float g_scores[Bb*Cc];      // softmax(f_scores)

// ---------------- 1. column sums of x ----------------
__global__ void colsum_kernel(const float* __restrict__ x) {
    int idx = blockIdx.x * blockDim.x + threadIdx.x;   // B*C*W = 262144
    int w = idx & 63;
    int c = (idx >> 6) & 255;
    int b = idx >> 14;
    const float* p = x + ((b*Cc + c)*Hh)*Ww + w;
    float s = 0.f;
    #pragma unroll 8
    for (int h = 0; h < Hh; h++) s += p[h*Ww];
    g_colsum[idx] = s;
}

// ---------------- 2. reduce wk over output channels ----------------
__global__ void wkred_kernel(const float* __restrict__ wk) {
    int idx = blockIdx.x * blockDim.x + threadIdx.x;   // C*9 = 2304
    if (idx >= Cc*9) return;
    int cp = idx / 9, tap = idx % 9;
    float s = 0.f;
    for (int c = 0; c < Cc; c++) s += wk[c*Cc*9 + cp*9 + tap];
    g_wkred[idx] = s;
}

// ---------------- 3. q_sum via column-sum algebra ----------------
// q_sum[b,c,w] = sum_{c',kh,kw} wq[c,c',kh,kw] * A_kh[b,c',w+kw-1]
// A_0 = S - x[last row], A_1 = S, A_2 = S - x[row 0]; A = 0 outside [0,W)
#define QS_KT 16
__global__ __launch_bounds__(256) void qsum_kernel(const float* __restrict__ x,
                                                   const float* __restrict__ wq) {
    int b = blockIdx.x >> 4;
    int cbase = (blockIdx.x & 15) * 16;   // 16 output channels per block
    int tid = threadIdx.x;
    int w  = tid & 63;
    int ty = tid >> 6;                    // 0..3 -> couts cbase + ty*4 + k

    __shared__ float As[3][QS_KT][66];
    __shared__ float Wsm[16][QS_KT*9];

    float acc[4] = {0.f, 0.f, 0.f, 0.f};

    for (int c0 = 0; c0 < Cc; c0 += QS_KT) {
        for (int idx = tid; idx < 3*QS_KT*66; idx += 256) {
            int wi = idx % 66;
            int ci = (idx / 66) % QS_KT;
            int r  = idx / (66*QS_KT);
            int wp = wi - 1;
            float v = 0.f;
            if (wp >= 0 && wp < Ww) {
                int ch = b*Cc + c0 + ci;
                float S = g_colsum[ch*Ww + wp];
                if (r == 0)      v = S - x[(ch*Hh + (Hh-1))*Ww + wp];
                else if (r == 1) v = S;
                else             v = S - x[(ch*Hh)*Ww + wp];
            }
            As[r][ci][wi] = v;
        }
        for (int idx = tid; idx < 16*QS_KT*9; idx += 256) {
            int col = idx % (QS_KT*9);
            int co  = idx / (QS_KT*9);
            Wsm[co][col] = wq[(cbase+co)*Cc*9 + c0*9 + col];
        }
        __syncthreads();
        #pragma unroll 4
        for (int ci = 0; ci < QS_KT; ci++) {
            #pragma unroll
            for (int kh = 0; kh < 3; kh++) {
                float a0 = As[kh][ci][w];
                float a1 = As[kh][ci][w+1];
                float a2 = As[kh][ci][w+2];
                #pragma unroll
                for (int k = 0; k < 4; k++) {
                    const float* wp = &Wsm[ty*4 + k][ci*9 + kh*3];
                    acc[k] = fmaf(wp[0], a0, acc[k]);
                    acc[k] = fmaf(wp[1], a1, acc[k]);
                    acc[k] = fmaf(wp[2], a2, acc[k]);
                }
            }
        }
        __syncthreads();
    }
    #pragma unroll
    for (int k = 0; k < 4; k++)
        g_qsum[(b*Cc + cbase + ty*4 + k)*Ww + w] = acc[k];
}

// ---------------- 4. k_sum ----------------
__global__ void ksum_kernel(const float* __restrict__ x) {
    int b = blockIdx.x;
    int w = threadIdx.x;   // 64
    float acc = 0.f;
    for (int cp = 0; cp < Cc; cp++) {
        int ch = b*Cc + cp;
        const float* sp = &g_colsum[ch*Ww];
        const float* x0 = x + (ch*Hh)*Ww;
        const float* xl = x0 + (Hh-1)*Ww;
        const float* wr = &g_wkred[cp*9];
        #pragma unroll
        for (int kw = 0; kw < 3; kw++) {
            int wp = w + kw - 1;
            if (wp < 0 || wp >= Ww) continue;
            float S = sp[wp];
            acc = fmaf(wr[0*3+kw], S - xl[wp], acc);
            acc = fmaf(wr[1*3+kw], S,          acc);
            acc = fmaf(wr[2*3+kw], S - x0[wp], acc);
        }
    }
    g_ksum[b*Ww + w] = acc;
}

// ---------------- 5. f_scores + softmax ----------------
__global__ __launch_bounds__(256) void scores_kernel() {
    int b = blockIdx.x;
    int c = threadIdx.x;   // 256
    __shared__ float ks[Ww];
    __shared__ float red[256];
    if (c < Ww) ks[c] = g_ksum[b*Ww + c];
    __syncthreads();
    const float* qp = &g_qsum[(b*Cc + c)*Ww];
    float f = 0.f;
    #pragma unroll 8
    for (int w = 0; w < Ww; w++) f = fmaf(qp[w], ks[w], f);
    f *= (1.0f / 32768.0f);   // 1/(sqrt(64)*64*64)

    red[c] = f; __syncthreads();
    for (int s = 128; s > 0; s >>= 1) {
        if (c < s) red[c] = fmaxf(red[c], red[c+s]);
        __syncthreads();
    }
    float mx = red[0]; __syncthreads();
    float e = expf(f - mx);
    red[c] = e; __syncthreads();
    for (int s = 128; s > 0; s >>= 1) {
        if (c < s) red[c] += red[c+s];
        __syncthreads();
    }
    g_scores[b*Cc + c] = e / red[0];
}

// ---------------- 6. fv conv (heavy) + fused epilogue ----------------
// out = relu((scores[b,c]*fv + x - mean)*gamma/sqrt(var+eps) + beta)
#define CK 8
__global__ __launch_bounds__(256) void conv_fused_kernel(
    const float* __restrict__ x,  const float* __restrict__ wv,
    const float* __restrict__ gamma, const float* __restrict__ beta,
    const float* __restrict__ rmean, const float* __restrict__ rvar,
    float* __restrict__ out)
{
    int b = blockIdx.z;
    int h = blockIdx.y;
    int cbase = blockIdx.x * 64;
    int tid = threadIdx.x;
    int tx = tid & 15;        // -> wbase = tx*4
    int ty = tid >> 4;        // -> couts cbase + ty*4 + co
    int wbase = tx * 4;

    __shared__ float xs[3][CK][68];     // padded row (68) for alignment
    __shared__ float ws[64][CK*9];      // ws[co][ci*9 + kh*3 + kw]

    float acc[4][4];
    #pragma unroll
    for (int i = 0; i < 4; i++)
        #pragma unroll
        for (int j = 0; j < 4; j++) acc[i][j] = 0.f;

    for (int c0 = 0; c0 < Cc; c0 += CK) {
        // stage x rows h-1..h+1 for CK input channels, with halo+zero pad
        for (int idx = tid; idx < 3*CK*66; idx += 256) {
            int wi = idx % 66;
            int ci = (idx / 66) % CK;
            int r  = idx / (66*CK);
            int hh = h + r - 1;
            int wp = wi - 1;
            float v = 0.f;
            if (hh >= 0 && hh < Hh && wp >= 0 && wp < Ww)
                v = x[((b*Cc + c0 + ci)*Hh + hh)*Ww + wp];
            xs[r][ci][wi] = v;
        }
        // stage weights: contiguous 72-float run per output channel
        for (int idx = tid; idx < 64*CK*9; idx += 256) {
            int col = idx % (CK*9);
            int co  = idx / (CK*9);
            ws[co][col] = wv[(cbase+co)*Cc*9 + c0*9 + col];
        }
        __syncthreads();

        #pragma unroll
        for (int ci = 0; ci < CK; ci++) {
            #pragma unroll
            for (int kh = 0; kh < 3; kh++) {
                float xv[6];
                #pragma unroll
                for (int q = 0; q < 6; q++) xv[q] = xs[kh][ci][wbase + q];
                #pragma unroll
                for (int co = 0; co < 4; co++) {
                    const float* wp = &ws[ty*4 + co][ci*9 + kh*3];
                    float w0 = wp[0], w1 = wp[1], w2 = wp[2];
                    #pragma unroll
                    for (int ow = 0; ow < 4; ow++) {
                        acc[co][ow] = fmaf(w0, xv[ow],   acc[co][ow]);
                        acc[co][ow] = fmaf(w1, xv[ow+1], acc[co][ow]);
                        acc[co][ow] = fmaf(w2, xv[ow+2], acc[co][ow]);
                    }
                }
            }
        }
        __syncthreads();
    }

    // epilogue: attention-scale + residual + BN(eval) + ReLU
    #pragma unroll
    for (int co = 0; co < 4; co++) {
        int c = cbase + ty*4 + co;
        float sc  = g_scores[b*Cc + c];
        float inv = gamma[c] * rsqrtf(rvar[c] + EPSV);
        float mb  = beta[c] - rmean[c] * inv;
        const float* xr = &x  [((b*Cc + c)*Hh + h)*Ww + wbase];
        float*       op = &out[((b*Cc + c)*Hh + h)*Ww + wbase];
        #pragma unroll
        for (int ow = 0; ow < 4; ow++) {
            float r = fmaf(sc, acc[co][ow], xr[ow]);
            r = fmaf(r, inv, mb);
            op[ow] = fmaxf(r, 0.f);
        }
    }
}

// ---------------- launcher ----------------
extern "C" void kernel_launch(void* const* d_in, const int* in_sizes, int n_in,
                              void* d_out, int out_size) {
    const float* x     = (const float*)d_in[0];
    const float* wq    = (const float*)d_in[1];
    const float* wk    = (const float*)d_in[2];
    const float* wv    = (const float*)d_in[3];
    const float* gamma = (const float*)d_in[4];
    const float* beta  = (const float*)d_in[5];
    const float* rmean = (const float*)d_in[6];
    const float* rvar  = (const float*)d_in[7];
    float* out = (float*)d_out;

    colsum_kernel<<<(Bb*Cc*Ww)/256, 256>>>(x);
    wkred_kernel<<<(Cc*9 + 255)/256, 256>>>(wk);
    qsum_kernel<<<Bb*16, 256>>>(x, wq);
    ksum_kernel<<<Bb, Ww>>>(x);
    scores_kernel<<<Bb, 256>>>();
    conv_fused_kernel<<<dim3(Cc/64, Hh, Bb), 256>>>(x, wv, gamma, beta, rmean, rvar, out);
}

// round 4
// speedup vs baseline: 5.4579x; 5.4579x over previous
#include <cuda_runtime.h>
#include <cuda_bf16.h>
#include <math.h>
#include <stdint.h>

#define Bb 16
#define Cc 256
#define Hh 64
#define Ww 64
#define EPSV 1e-5f
#define PAD 66

// ---------------- scratch (no allocations allowed) ----------------
__device__ float g_colsum[Bb*Cc*Ww];
__device__ float g_qsum  [Bb*Cc*Ww];
__device__ float g_kpart [16*Bb*Ww];
__device__ float g_wkred [Cc*9];
__device__ float g_scores[Bb*Cc];
__device__ __nv_bfloat16 g_xT[Bb*PAD*PAD*Cc];  // padded, channel-last, bf16
__device__ __nv_bfloat16 g_wT[9*Cc*Cc];        // wT[tap][co][ci]

// ================= portable PTX helpers (compute_100-safe) =================
__device__ __forceinline__ uint32_t smem_u32(const void* p) {
    uint32_t a;
    asm("{ .reg .u64 t; cvta.to.shared.u64 t, %1; cvt.u32.u64 %0, t; }" : "=r"(a) : "l"(p));
    return a;
}
#define SWZ(o) ((o) ^ (((o) >> 3) & 0x70))

#define CPASYNC(dst, src) \
    asm volatile("cp.async.cg.shared.global [%0], [%1], 16;" :: "r"(dst), "l"(src) : "memory")
#define CPCOMMIT() asm volatile("cp.async.commit_group;" ::: "memory")
#define CPWAIT1()  asm volatile("cp.async.wait_group 1;" ::: "memory")

__device__ __forceinline__ void ldsm_x4(uint32_t* r, uint32_t addr) {
    asm volatile("ldmatrix.sync.aligned.m8n8.x4.shared.b16 {%0,%1,%2,%3}, [%4];"
        : "=r"(r[0]), "=r"(r[1]), "=r"(r[2]), "=r"(r[3]) : "r"(addr));
}
__device__ __forceinline__ void mma16816(float* d, const uint32_t* a, const uint32_t* b) {
    asm volatile("mma.sync.aligned.m16n8k16.row.col.f32.bf16.bf16.f32 "
        "{%0,%1,%2,%3}, {%4,%5,%6,%7}, {%8,%9}, {%0,%1,%2,%3};"
        : "+f"(d[0]), "+f"(d[1]), "+f"(d[2]), "+f"(d[3])
        : "r"(a[0]), "r"(a[1]), "r"(a[2]), "r"(a[3]), "r"(b[0]), "r"(b[1]));
}

// ================= aux path (exact fp32 scores) =================
__global__ void colsum_kernel(const float* __restrict__ x) {
    int idx = blockIdx.x * blockDim.x + threadIdx.x;
    const float* p = x + ((idx >> 6) * Hh) * Ww + (idx & 63);
    float s = 0.f;
    #pragma unroll 8
    for (int h = 0; h < Hh; h++) s += p[h*Ww];
    g_colsum[idx] = s;
}

__global__ void wkred_kernel(const float* __restrict__ wk) {
    int idx = blockIdx.x * blockDim.x + threadIdx.x;
    if (idx >= Cc*9) return;
    int cp = idx / 9, tap = idx % 9;
    float s = 0.f;
    for (int c = 0; c < Cc; c++) s += wk[c*Cc*9 + cp*9 + tap];
    g_wkred[idx] = s;
}

#define QS_KT 16
__global__ __launch_bounds__(256) void qsum_kernel(const float* __restrict__ x,
                                                   const float* __restrict__ wq) {
    int b = blockIdx.x >> 4;
    int cbase = (blockIdx.x & 15) * 16;
    int tid = threadIdx.x;
    int w = tid & 63, ty = tid >> 6;
    __shared__ float As[3][QS_KT][66];
    __shared__ float Wsm[16][QS_KT*9];
    float acc[4] = {0.f, 0.f, 0.f, 0.f};
    for (int c0 = 0; c0 < Cc; c0 += QS_KT) {
        for (int idx = tid; idx < 3*QS_KT*66; idx += 256) {
            int wi = idx % 66, ci = (idx/66) % QS_KT, r = idx/(66*QS_KT);
            int wp = wi - 1;
            float v = 0.f;
            if (wp >= 0 && wp < Ww) {
                int ch = b*Cc + c0 + ci;
                float S = g_colsum[ch*Ww + wp];
                if (r == 0)      v = S - x[(ch*Hh + (Hh-1))*Ww + wp];
                else if (r == 1) v = S;
                else             v = S - x[(ch*Hh)*Ww + wp];
            }
            As[r][ci][wi] = v;
        }
        for (int idx = tid; idx < 16*QS_KT*9; idx += 256)
            Wsm[idx/(QS_KT*9)][idx%(QS_KT*9)] = wq[(cbase + idx/(QS_KT*9))*Cc*9 + c0*9 + idx%(QS_KT*9)];
        __syncthreads();
        #pragma unroll 4
        for (int ci = 0; ci < QS_KT; ci++)
            #pragma unroll
            for (int kh = 0; kh < 3; kh++) {
                float a0 = As[kh][ci][w], a1 = As[kh][ci][w+1], a2 = As[kh][ci][w+2];
                #pragma unroll
                for (int k = 0; k < 4; k++) {
                    const float* wp = &Wsm[ty*4 + k][ci*9 + kh*3];
                    acc[k] = fmaf(wp[0], a0, acc[k]);
                    acc[k] = fmaf(wp[1], a1, acc[k]);
                    acc[k] = fmaf(wp[2], a2, acc[k]);
                }
            }
        __syncthreads();
    }
    #pragma unroll
    for (int k = 0; k < 4; k++)
        g_qsum[(b*Cc + cbase + ty*4 + k)*Ww + w] = acc[k];
}

__global__ void ksum_kernel(const float* __restrict__ x) {
    int cpc = blockIdx.x;
    int b = blockIdx.y;
    int w = threadIdx.x;
    float acc = 0.f;
    for (int cp = cpc*16; cp < cpc*16 + 16; cp++) {
        int ch = b*Cc + cp;
        const float* sp = &g_colsum[ch*Ww];
        const float* x0 = x + (ch*Hh)*Ww;
        const float* xl = x0 + (Hh-1)*Ww;
        const float* wr = &g_wkred[cp*9];
        #pragma unroll
        for (int kw = 0; kw < 3; kw++) {
            int wp = w + kw - 1;
            if (wp < 0 || wp >= Ww) continue;
            float S = sp[wp];
            acc = fmaf(wr[0*3+kw], S - xl[wp], acc);
            acc = fmaf(wr[1*3+kw], S,          acc);
            acc = fmaf(wr[2*3+kw], S - x0[wp], acc);
        }
    }
    g_kpart[(cpc*Bb + b)*Ww + w] = acc;
}

__global__ __launch_bounds__(256) void scores_kernel() {
    int b = blockIdx.x;
    int c = threadIdx.x;
    __shared__ float ks[Ww];
    __shared__ float red[256];
    if (c < Ww) {
        float s = 0.f;
        #pragma unroll
        for (int i = 0; i < 16; i++) s += g_kpart[(i*Bb + b)*Ww + c];
        ks[c] = s;
    }
    __syncthreads();
    const float* qp = &g_qsum[(b*Cc + c)*Ww];
    float f = 0.f;
    #pragma unroll 8
    for (int w = 0; w < Ww; w++) f = fmaf(qp[w], ks[w], f);
    f *= (1.0f / 32768.0f);
    red[c] = f; __syncthreads();
    for (int s = 128; s > 0; s >>= 1) { if (c < s) red[c] = fmaxf(red[c], red[c+s]); __syncthreads(); }
    float mx = red[0]; __syncthreads();
    float e = expf(f - mx);
    red[c] = e; __syncthreads();
    for (int s = 128; s > 0; s >>= 1) { if (c < s) red[c] += red[c+s]; __syncthreads(); }
    g_scores[b*Cc + c] = e / red[0];
}

// ================= bf16 transforms =================
__global__ void zerofill_kernel() {
    int idx = blockIdx.x * 256 + threadIdx.x;
    ((uint32_t*)g_xT)[idx] = 0u;
}

__global__ void wt_kernel(const float* __restrict__ wv) {
    int idx = blockIdx.x * 256 + threadIdx.x;   // 9*256*256
    int ci = idx & 255, co = (idx >> 8) & 255, tap = idx >> 16;
    g_wT[idx] = __float2bfloat16(wv[(co*Cc + ci)*9 + tap]);
}

__global__ __launch_bounds__(256) void xpose_kernel(const float* __restrict__ x) {
    __shared__ float sm[64][65];
    int ci0 = blockIdx.x * 64;
    int h = blockIdx.y, b = blockIdx.z;
    int tid = threadIdx.x;
    #pragma unroll
    for (int k = 0; k < 16; k++) {
        int e = k*256 + tid;
        int ci = e >> 6, w = e & 63;
        sm[ci][w] = x[((b*Cc + ci0 + ci)*Hh + h)*Ww + w];
    }
    __syncthreads();
    #pragma unroll
    for (int k = 0; k < 8; k++) {
        int e = k*256 + tid;
        int w = e >> 5, c2 = (e & 31) * 2;
        __nv_bfloat162 v = __floats2bfloat162_rn(sm[c2][w], sm[c2+1][w]);
        *(__nv_bfloat162*)&g_xT[((b*PAD + h + 1)*PAD + (w + 1))*Cc + ci0 + c2] = v;
    }
}

// ================= mma.sync implicit conv + fused epilogue =================
// CTA: M=128 (co), N=256 (4 h-rows x 64 w). 8 warps, each 64(co) x 64(n=1 row).
#define A_BYTES 16384
#define B_BYTES 32768
#define STAGE   (A_BYTES + B_BYTES)
#define SMEM_CONV (2*STAGE)

__global__ __launch_bounds__(256) void conv_mma_kernel(
    const float* __restrict__ x,
    const float* __restrict__ gamma, const float* __restrict__ beta,
    const float* __restrict__ rmean, const float* __restrict__ rvar,
    float* __restrict__ out)
{
    extern __shared__ char smem[];
    uint32_t sb = smem_u32(smem);
    int tid = threadIdx.x;
    int wid = tid >> 5, lane = tid & 31;
    int cbase = blockIdx.x * 128;
    int h0 = blockIdx.y * 4;
    int b  = blockIdx.z;
    int wm = wid >> 2;            // 0..1 : co half (64 rows)
    int wn = wid & 3;             // 0..3 : h row (64 cols of n)

    const char* wT_b = (const char*)g_wT;
    const char* xT_b = (const char*)g_xT;

    float acc[4][8][4];
    #pragma unroll
    for (int i = 0; i < 4; i++)
        #pragma unroll
        for (int j = 0; j < 8; j++)
            #pragma unroll
            for (int k = 0; k < 4; k++) acc[i][j][k] = 0.f;

    // ---- staging helper (cp.async), s = tap*4 + chunk ----
    auto stage = [&](int s) {
        int buf = s & 1;
        int tap = s >> 2;
        int ci0 = (s & 3) * 64;
        int dh = tap / 3 - 1, dw = tap % 3 - 1;
        uint32_t ab = sb + buf*STAGE;
        uint32_t bbs = ab + A_BYTES;
        #pragma unroll
        for (int it = 0; it < 4; it++) {        // A: 128 rows x 128B
            int q = it*256 + tid;
            int m = q >> 3, j = q & 7;
            const char* src = wT_b + (((tap*Cc + cbase + m)*Cc + ci0 + j*8) << 1);
            CPASYNC(ab + SWZ(m*128 + j*16), src);
        }
        #pragma unroll
        for (int it = 0; it < 8; it++) {        // B: 256 rows x 128B
            int p = it*256 + tid;
            int n = p >> 3, j = p & 7;
            int r = n >> 6, w = n & 63;
            int hp = h0 + r + dh + 1, wp = w + dw + 1;   // in [0,65]
            const char* src = xT_b + ((((b*PAD + hp)*PAD + wp)*Cc + ci0 + j*8) << 1);
            CPASYNC(bbs + SWZ(n*128 + j*16), src);
        }
    };

    stage(0); CPCOMMIT();

    for (int s = 0; s < 36; s++) {
        if (s + 1 < 36) stage(s + 1);
        CPCOMMIT();
        CPWAIT1();
        __syncthreads();

        uint32_t ab = sb + (s & 1)*STAGE;
        uint32_t bbs = ab + A_BYTES;

        #pragma unroll
        for (int ks = 0; ks < 4; ks++) {
            uint32_t afr[4][4], bfr[4][4];
            #pragma unroll
            for (int mt = 0; mt < 4; mt++) {
                int row = wm*64 + mt*16 + (lane & 15);
                int col = ks*32 + ((lane >> 4) << 4);
                ldsm_x4(afr[mt], ab + SWZ(row*128 + col));
            }
            #pragma unroll
            for (int nt2 = 0; nt2 < 4; nt2++) {
                int row = wn*64 + nt2*16 + (lane & 7) + ((lane >> 4) << 3);
                int col = ks*32 + (((lane >> 3) & 1) << 4);
                ldsm_x4(bfr[nt2], bbs + SWZ(row*128 + col));
            }
            #pragma unroll
            for (int mt = 0; mt < 4; mt++)
                #pragma unroll
                for (int nt2 = 0; nt2 < 4; nt2++) {
                    mma16816(acc[mt][nt2*2],     afr[mt], &bfr[nt2][0]);
                    mma16816(acc[mt][nt2*2 + 1], afr[mt], &bfr[nt2][2]);
                }
        }
        __syncthreads();
    }

    // ---- fused epilogue: relu((score*fv + x - mean)*gamma*rsqrt(var+eps) + beta)
    int h = h0 + wn;
    #pragma unroll
    for (int mt = 0; mt < 4; mt++) {
        #pragma unroll
        for (int half = 0; half < 2; half++) {
            int c = cbase + wm*64 + mt*16 + (lane >> 2) + half*8;
            float sc  = g_scores[b*Cc + c];
            float inv = gamma[c] * rsqrtf(rvar[c] + EPSV);
            float mb  = beta[c] - rmean[c] * inv;
            const float* xr = &x  [((b*Cc + c)*Hh + h)*Ww];
            float*       op = &out[((b*Cc + c)*Hh + h)*Ww];
            #pragma unroll
            for (int nt = 0; nt < 8; nt++) {
                int w = nt*8 + (lane & 3)*2;
                float2 xv = *(const float2*)&xr[w];
                float v0 = acc[mt][nt][half*2 + 0];
                float v1 = acc[mt][nt][half*2 + 1];
                float2 ov;
                ov.x = fmaxf(fmaf(fmaf(sc, v0, xv.x), inv, mb), 0.f);
                ov.y = fmaxf(fmaf(fmaf(sc, v1, xv.y), inv, mb), 0.f);
                *(float2*)&op[w] = ov;
            }
        }
    }
}

// ================= launcher =================
extern "C" void kernel_launch(void* const* d_in, const int* in_sizes, int n_in,
                              void* d_out, int out_size) {
    const float* x     = (const float*)d_in[0];
    const float* wq    = (const float*)d_in[1];
    const float* wk    = (const float*)d_in[2];
    const float* wv    = (const float*)d_in[3];
    const float* gamma = (const float*)d_in[4];
    const float* beta  = (const float*)d_in[5];
    const float* rmean = (const float*)d_in[6];
    const float* rvar  = (const float*)d_in[7];
    float* out = (float*)d_out;

    // scores path (exact fp32)
    colsum_kernel<<<(Bb*Cc*Ww)/256, 256>>>(x);
    wkred_kernel<<<(Cc*9 + 255)/256, 256>>>(wk);
    qsum_kernel<<<Bb*16, 256>>>(x, wq);
    ksum_kernel<<<dim3(16, Bb), 64>>>(x);
    scores_kernel<<<Bb, 256>>>();

    // bf16 transforms
    zerofill_kernel<<<(Bb*PAD*PAD*Cc/2)/256, 256>>>();
    wt_kernel<<<(9*Cc*Cc)/256, 256>>>(wv);
    xpose_kernel<<<dim3(4, Hh, Bb), 256>>>(x);

    // mma.sync conv + fused epilogue
    cudaFuncSetAttribute(conv_mma_kernel,
                         cudaFuncAttributeMaxDynamicSharedMemorySize, SMEM_CONV);
    conv_mma_kernel<<<dim3(2, 16, Bb), 256, SMEM_CONV>>>(x, gamma, beta, rmean, rvar, out);
}

// round 7
// speedup vs baseline: 7.6085x; 1.3940x over previous
#include <cuda_runtime.h>
#include <cuda_bf16.h>
#include <math.h>
#include <stdint.h>

#define Bb 16
#define Cc 256
#define Hh 64
#define Ww 64
#define EPSV 1e-5f
#define PAD 66

#define XSCALE 20.0f
#define WSCALE 1024.0f
#define DEQ    (1.0f/20480.0f)

// ---------------- scratch (no allocations allowed) ----------------
__device__ float g_colsum[Bb*Cc*Ww];
__device__ float g_qsum  [Bb*Cc*Ww];
__device__ float g_kpart [64*Bb*Ww];
__device__ float g_wkred [Cc*9];
__device__ float g_scores[Bb*Cc];
__device__ __align__(256) uint8_t g_x8[Bb*PAD*PAD*Cc];   // padded, channel-last, s8 (x*20)
__device__ __align__(256) uint8_t g_w8[9*Cc*Cc];         // w8[tap][co][ci], s8 (w*1024)

// ================= portable PTX helpers (compute_100-safe) =================
__device__ __forceinline__ uint32_t smem_u32(const void* p) {
    uint32_t a;
    asm("{ .reg .u64 t; cvta.to.shared.u64 t, %1; cvt.u32.u64 %0, t; }" : "=r"(a) : "l"(p));
    return a;
}
#define SWZ(o) ((o) ^ (((o) >> 3) & 0x70))

#define CPASYNC(dst, src) \
    asm volatile("cp.async.cg.shared.global [%0], [%1], 16;" :: "r"(dst), "l"(src) : "memory")
#define CPCOMMIT() asm volatile("cp.async.commit_group;" ::: "memory")
#define CPWAIT1()  asm volatile("cp.async.wait_group 1;" ::: "memory")

__device__ __forceinline__ void ldsm_x4(uint32_t* r, uint32_t addr) {
    asm volatile("ldmatrix.sync.aligned.m8n8.x4.shared.b16 {%0,%1,%2,%3}, [%4];"
        : "=r"(r[0]), "=r"(r[1]), "=r"(r[2]), "=r"(r[3]) : "r"(addr));
}
// int8 IMMA: m16n8k32, s32 accum (sm_75+, rock-solid on sm_100)
__device__ __forceinline__ void mma16832i(int* d, const uint32_t* a, const uint32_t* b) {
    asm volatile("mma.sync.aligned.m16n8k32.row.col.s32.s8.s8.s32 "
        "{%0,%1,%2,%3}, {%4,%5,%6,%7}, {%8,%9}, {%0,%1,%2,%3};"
        : "+r"(d[0]), "+r"(d[1]), "+r"(d[2]), "+r"(d[3])
        : "r"(a[0]), "r"(a[1]), "r"(a[2]), "r"(a[3]), "r"(b[0]), "r"(b[1]));
}
__device__ __forceinline__ uint32_t pack_s8x4(float a, float b, float c, float d) {
    int q0 = __float2int_rn(fminf(fmaxf(a, -127.f), 127.f));
    int q1 = __float2int_rn(fminf(fmaxf(b, -127.f), 127.f));
    int q2 = __float2int_rn(fminf(fmaxf(c, -127.f), 127.f));
    int q3 = __float2int_rn(fminf(fmaxf(d, -127.f), 127.f));
    return (q0 & 255) | ((q1 & 255) << 8) | ((q2 & 255) << 16) | ((q3 & 255) << 24);
}

// ================= aux path (exact fp32 scores) =================
__global__ void colsum_kernel(const float* __restrict__ x) {
    int idx = blockIdx.x * blockDim.x + threadIdx.x;
    const float* p = x + ((idx >> 6) * Hh) * Ww + (idx & 63);
    float s = 0.f;
    #pragma unroll 8
    for (int h = 0; h < Hh; h++) s += p[h*Ww];
    g_colsum[idx] = s;
}

__global__ void wkred_kernel(const float* __restrict__ wk) {
    int idx = blockIdx.x * blockDim.x + threadIdx.x;
    if (idx >= Cc*9) return;
    int cp = idx / 9, tap = idx % 9;
    float s = 0.f;
    for (int c = 0; c < Cc; c++) s += wk[c*Cc*9 + cp*9 + tap];
    g_wkred[idx] = s;
}

#define QS_KT 16
__global__ __launch_bounds__(256) void qsum_kernel(const float* __restrict__ x,
                                                   const float* __restrict__ wq) {
    int b = blockIdx.x >> 4;
    int cbase = (blockIdx.x & 15) * 16;
    int tid = threadIdx.x;
    int w = tid & 63, ty = tid >> 6;
    __shared__ float As[3][QS_KT][66];
    __shared__ float Wsm[16][QS_KT*9];
    float acc[4] = {0.f, 0.f, 0.f, 0.f};
    for (int c0 = 0; c0 < Cc; c0 += QS_KT) {
        for (int idx = tid; idx < 3*QS_KT*66; idx += 256) {
            int wi = idx % 66, ci = (idx/66) % QS_KT, r = idx/(66*QS_KT);
            int wp = wi - 1;
            float v = 0.f;
            if (wp >= 0 && wp < Ww) {
                int ch = b*Cc + c0 + ci;
                float S = g_colsum[ch*Ww + wp];
                if (r == 0)      v = S - x[(ch*Hh + (Hh-1))*Ww + wp];
                else if (r == 1) v = S;
                else             v = S - x[(ch*Hh)*Ww + wp];
            }
            As[r][ci][wi] = v;
        }
        for (int idx = tid; idx < 16*QS_KT*9; idx += 256)
            Wsm[idx/(QS_KT*9)][idx%(QS_KT*9)] = wq[(cbase + idx/(QS_KT*9))*Cc*9 + c0*9 + idx%(QS_KT*9)];
        __syncthreads();
        #pragma unroll 4
        for (int ci = 0; ci < QS_KT; ci++)
            #pragma unroll
            for (int kh = 0; kh < 3; kh++) {
                float a0 = As[kh][ci][w], a1 = As[kh][ci][w+1], a2 = As[kh][ci][w+2];
                #pragma unroll
                for (int k = 0; k < 4; k++) {
                    const float* wp = &Wsm[ty*4 + k][ci*9 + kh*3];
                    acc[k] = fmaf(wp[0], a0, acc[k]);
                    acc[k] = fmaf(wp[1], a1, acc[k]);
                    acc[k] = fmaf(wp[2], a2, acc[k]);
                }
            }
        __syncthreads();
    }
    #pragma unroll
    for (int k = 0; k < 4; k++)
        g_qsum[(b*Cc + cbase + ty*4 + k)*Ww + w] = acc[k];
}

// 64 partials: grid (16 cpc, Bb), block 256 = 64 w x 4 sub (4 cp each)
__global__ __launch_bounds__(256) void ksum_kernel(const float* __restrict__ x) {
    int cpc = blockIdx.x;
    int b = blockIdx.y;
    int tid = threadIdx.x;
    int w = tid & 63, sub = tid >> 6;
    float acc = 0.f;
    int cp0 = cpc*16 + sub*4;
    #pragma unroll
    for (int k = 0; k < 4; k++) {
        int cp = cp0 + k;
        int ch = b*Cc + cp;
        const float* sp = &g_colsum[ch*Ww];
        const float* x0 = x + (ch*Hh)*Ww;
        const float* xl = x0 + (Hh-1)*Ww;
        const float* wr = &g_wkred[cp*9];
        #pragma unroll
        for (int kw = 0; kw < 3; kw++) {
            int wp = w + kw - 1;
            if (wp < 0 || wp >= Ww) continue;
            float S = sp[wp];
            acc = fmaf(wr[0*3+kw], S - xl[wp], acc);
            acc = fmaf(wr[1*3+kw], S,          acc);
            acc = fmaf(wr[2*3+kw], S - x0[wp], acc);
        }
    }
    g_kpart[((cpc*4 + sub)*Bb + b)*Ww + w] = acc;
}

__global__ __launch_bounds__(256) void scores_kernel() {
    int b = blockIdx.x;
    int c = threadIdx.x;
    __shared__ float ks[Ww];
    __shared__ float red[256];
    if (c < Ww) {
        float s = 0.f;
        #pragma unroll
        for (int i = 0; i < 64; i++) s += g_kpart[(i*Bb + b)*Ww + c];
        ks[c] = s;
    }
    __syncthreads();
    const float* qp = &g_qsum[(b*Cc + c)*Ww];
    float f = 0.f;
    #pragma unroll 8
    for (int w = 0; w < Ww; w++) f = fmaf(qp[w], ks[w], f);
    f *= (1.0f / 32768.0f);
    red[c] = f; __syncthreads();
    for (int s = 128; s > 0; s >>= 1) { if (c < s) red[c] = fmaxf(red[c], red[c+s]); __syncthreads(); }
    float mx = red[0]; __syncthreads();
    float e = expf(f - mx);
    red[c] = e; __syncthreads();
    for (int s = 128; s > 0; s >>= 1) { if (c < s) red[c] += red[c+s]; __syncthreads(); }
    g_scores[b*Cc + c] = e / red[0];
}

// ================= int8 transforms =================
__global__ void zerofill_kernel() {
    int idx = blockIdx.x * 256 + threadIdx.x;   // 4,460,544 words
    ((uint32_t*)g_x8)[idx] = 0u;
}

// w8[tap][co][ci] = s8(round(wv[co][ci][tap] * 1024))
__global__ void wt_kernel(const float* __restrict__ wv) {
    int idx = blockIdx.x * 256 + threadIdx.x;   // 9*256*64 quads
    int ci4 = (idx & 63) * 4;
    int co  = (idx >> 6) & 255;
    int tap = idx >> 14;
    float w0 = wv[(co*Cc + ci4    )*9 + tap] * WSCALE;
    float w1 = wv[(co*Cc + ci4 + 1)*9 + tap] * WSCALE;
    float w2 = wv[(co*Cc + ci4 + 2)*9 + tap] * WSCALE;
    float w3 = wv[(co*Cc + ci4 + 3)*9 + tap] * WSCALE;
    *(uint32_t*)&g_w8[(tap*Cc + co)*Cc + ci4] = pack_s8x4(w0, w1, w2, w3);
}

__global__ __launch_bounds__(256) void xpose_kernel(const float* __restrict__ x) {
    __shared__ float sm[64][65];
    int ci0 = blockIdx.x * 64;
    int h = blockIdx.y, b = blockIdx.z;
    int tid = threadIdx.x;
    #pragma unroll
    for (int k = 0; k < 16; k++) {
        int e = k*256 + tid;
        int ci = e >> 6, w = e & 63;
        sm[ci][w] = x[((b*Cc + ci0 + ci)*Hh + h)*Ww + w];
    }
    __syncthreads();
    #pragma unroll
    for (int k = 0; k < 4; k++) {
        int e = k*256 + tid;           // 1024 u32 = 64w x 16 ci-quads
        int w = e >> 4, c4 = (e & 15) * 4;
        *(uint32_t*)&g_x8[((b*PAD + h + 1)*PAD + (w + 1))*Cc + ci0 + c4] =
            pack_s8x4(sm[c4+0][w]*XSCALE, sm[c4+1][w]*XSCALE,
                      sm[c4+2][w]*XSCALE, sm[c4+3][w]*XSCALE);
    }
}

// ================= int8 mma implicit conv + fused epilogue =================
// CTA: M=128 (co), N=256 (4 h-rows x 64 w). 8 warps, each 64(co) x 64(n).
// B staged as 6x66 halo window per ci-chunk (128 ci = 128B rows), 2 chunks.
#define BW_ROWS  (6*66)
#define BW_BYTES (BW_ROWS*128)          // 50688
#define A0_OFF   (2*BW_BYTES)           // 101376
#define A_BYTES  16384
#define SMEM_CONV (2*BW_BYTES + 2*A_BYTES)   // 134144

__global__ __launch_bounds__(256) void conv_mma_kernel(
    const float* __restrict__ x,
    const float* __restrict__ gamma, const float* __restrict__ beta,
    const float* __restrict__ rmean, const float* __restrict__ rvar,
    float* __restrict__ out)
{
    extern __shared__ char smem[];
    uint32_t sb = smem_u32(smem);
    int tid = threadIdx.x;
    int wid = tid >> 5, lane = tid & 31;
    int cbase = blockIdx.x * 128;
    int h0 = blockIdx.y * 4;
    int b  = blockIdx.z;
    int wm = wid >> 2;            // 0..1 : co half
    int wn = wid & 3;             // 0..3 : h row

    const char* w8_b = (const char*)g_w8;
    const char* x8_b = (const char*)g_x8;

    int acc[4][8][4];
    #pragma unroll
    for (int i = 0; i < 4; i++)
        #pragma unroll
        for (int j = 0; j < 8; j++)
            #pragma unroll
            for (int k = 0; k < 4; k++) acc[i][j][k] = 0;

    // ---- stage A (weights) for s = chunk*9 + tap ----
    auto stageA = [&](int s) {
        int tap = s % 9, chunk = s / 9;
        int ci0 = chunk * 128;
        uint32_t ab = sb + A0_OFF + (s & 1) * A_BYTES;
        const char* base = w8_b + (size_t)(tap*Cc + cbase)*Cc + ci0;
        #pragma unroll
        for (int it = 0; it < 4; it++) {
            int q = it*256 + tid;
            int m = q >> 3, j = q & 7;
            CPASYNC(ab + SWZ(m*128 + j*16), base + m*Cc + j*16);
        }
    };
    // ---- stage B halo window (6 rows x 66 w x 128 ci) ----
    auto stageB = [&](int chunk) {
        uint32_t bb = sb + (chunk & 1) * BW_BYTES;
        const char* base = x8_b + ((size_t)(b*PAD + h0)*PAD)*Cc + chunk*128;
        for (int idx = tid; idx < BW_ROWS*8; idx += 256) {
            int j = idx >> 3, seg = idx & 7;
            int hl = j / 66, wl = j - hl*66;
            CPASYNC(bb + SWZ(j*128 + seg*16), base + (hl*PAD + wl)*Cc + seg*16);
        }
    };

    stageB(0);
    stageA(0);
    CPCOMMIT();

    for (int s = 0; s < 18; s++) {
        if (s + 1 < 18) {
            stageA(s + 1);
            if ((s + 1) % 9 == 0) stageB((s + 1) / 9);
        }
        CPCOMMIT();
        CPWAIT1();
        __syncthreads();

        int tap = s % 9;
        int dh = tap / 3 - 1, dw = tap % 3 - 1;
        uint32_t ab = sb + A0_OFF + (s & 1) * A_BYTES;
        uint32_t bb = sb + ((s / 9) & 1) * BW_BYTES;
        int bjbase = (wn + dh + 1)*66 + dw + 1;

        #pragma unroll
        for (int ks = 0; ks < 4; ks++) {
            uint32_t afr[4][4], bfr[4][4];
            #pragma unroll
            for (int mt = 0; mt < 4; mt++) {
                int row = wm*64 + mt*16 + (lane & 15);
                int col = ks*32 + ((lane >> 4) << 4);
                ldsm_x4(afr[mt], ab + SWZ(row*128 + col));
            }
            #pragma unroll
            for (int nt2 = 0; nt2 < 4; nt2++) {
                int j = bjbase + nt2*16 + (lane & 7) + ((lane >> 4) << 3);
                int col = ks*32 + (((lane >> 3) & 1) << 4);
                ldsm_x4(bfr[nt2], bb + SWZ(j*128 + col));
            }
            #pragma unroll
            for (int mt = 0; mt < 4; mt++)
                #pragma unroll
                for (int nt2 = 0; nt2 < 4; nt2++) {
                    mma16832i(acc[mt][nt2*2],     afr[mt], &bfr[nt2][0]);
                    mma16832i(acc[mt][nt2*2 + 1], afr[mt], &bfr[nt2][2]);
                }
        }
        __syncthreads();
    }

    // ---- fused epilogue (dequant 1/(20*1024) folded into score) ----
    int h = h0 + wn;
    #pragma unroll
    for (int mt = 0; mt < 4; mt++) {
        #pragma unroll
        for (int half = 0; half < 2; half++) {
            int c = cbase + wm*64 + mt*16 + (lane >> 2) + half*8;
            float sc  = g_scores[b*Cc + c] * DEQ;
            float inv = gamma[c] * rsqrtf(rvar[c] + EPSV);
            float mb  = beta[c] - rmean[c] * inv;
            const float* xr = &x  [((b*Cc + c)*Hh + h)*Ww];
            float*       op = &out[((b*Cc + c)*Hh + h)*Ww];
            #pragma unroll
            for (int nt = 0; nt < 8; nt++) {
                int w = nt*8 + (lane & 3)*2;
                float2 xv = *(const float2*)&xr[w];
                float v0 = (float)acc[mt][nt][half*2 + 0];
                float v1 = (float)acc[mt][nt][half*2 + 1];
                float2 ov;
                ov.x = fmaxf(fmaf(fmaf(sc, v0, xv.x), inv, mb), 0.f);
                ov.y = fmaxf(fmaf(fmaf(sc, v1, xv.y), inv, mb), 0.f);
                *(float2*)&op[w] = ov;
            }
        }
    }
}

// ================= launcher =================
extern "C" void kernel_launch(void* const* d_in, const int* in_sizes, int n_in,
                              void* d_out, int out_size) {
    const float* x     = (const float*)d_in[0];
    const float* wq    = (const float*)d_in[1];
    const float* wk    = (const float*)d_in[2];
    const float* wv    = (const float*)d_in[3];
    const float* gamma = (const float*)d_in[4];
    const float* beta  = (const float*)d_in[5];
    const float* rmean = (const float*)d_in[6];
    const float* rvar  = (const float*)d_in[7];
    float* out = (float*)d_out;

    // scores path (exact fp32)
    colsum_kernel<<<(Bb*Cc*Ww)/256, 256>>>(x);
    wkred_kernel<<<(Cc*9 + 255)/256, 256>>>(wk);
    qsum_kernel<<<Bb*16, 256>>>(x, wq);
    ksum_kernel<<<dim3(16, Bb), 256>>>(x);
    scores_kernel<<<Bb, 256>>>();

    // int8 transforms
    zerofill_kernel<<<(Bb*PAD*PAD*Cc/4)/256, 256>>>();
    wt_kernel<<<(9*Cc*Cc/4)/256, 256>>>(wv);
    xpose_kernel<<<dim3(4, Hh, Bb), 256>>>(x);

    // int8 mma conv + fused epilogue
    cudaFuncSetAttribute(conv_mma_kernel,
                         cudaFuncAttributeMaxDynamicSharedMemorySize, SMEM_CONV);
    conv_mma_kernel<<<dim3(2, 16, Bb), 256, SMEM_CONV>>>(x, gamma, beta, rmean, rvar, out);
}